// round 2
// baseline (speedup 1.0000x reference)
#include <cuda_runtime.h>
#include <math.h>

// x: [B=4, C=64, H=64, W=64, D=64] fp32
// out = x + irfftn(delta), delta = (gate-1)*rfftn(x) on corner [16,16,9]
#define NPLANES 16384   // B*C*H
#define NBC     256     // B*C
#define GATE_DIM 2304   // 16*16*9
#define NCOL    144     // 16 ky * 9 kz

// Scratch (static device allocations — allowed)
__device__ float2 g_Y[NPLANES * NCOL];     // 18.9 MB intermediate spectrum
__device__ float  g_planesum[NPLANES];
__device__ float  g_gate[4 * GATE_DIM];    // (sigmoid-1)/64^3 per (b,kx,ky,kz)

#define INV_N3 (1.0f / 262144.0f)

// tw[t] = (cos(2*pi*t/64), sin(2*pi*t/64))
__device__ __forceinline__ void fill_tw(float2* tw, int tid) {
    if (tid < 64) {
        float s, c;
        sincospif((float)tid * (1.0f / 32.0f), &s, &c);
        tw[tid] = make_float2(c, s);
    }
}

// ---------------------------------------------------------------------------
// Kernel 1: per-plane (b,c,h): plane sum, z-DFT (9 modes), y-DFT (16 modes)
// ---------------------------------------------------------------------------
__global__ void __launch_bounds__(256) k_fwd(const float* __restrict__ x) {
    __shared__ float  xs[64 * 65];        // [w][d], stride 65: conflict-free
    __shared__ float2 Zs[64 * 9];         // [w][kz]
    __shared__ float2 tw[64];
    __shared__ float  red[8];

    const int plane = blockIdx.x;
    const int tid   = threadIdx.x;
    fill_tw(tw, tid);

    // Load plane, accumulate sum for pooling
    const float* xp = x + (size_t)plane * 4096;
    float psum = 0.0f;
    #pragma unroll
    for (int i = tid; i < 4096; i += 256) {
        float v = xp[i];
        xs[(i >> 6) * 65 + (i & 63)] = v;
        psum += v;
    }
    // warp + block reduce
    #pragma unroll
    for (int o = 16; o > 0; o >>= 1) psum += __shfl_down_sync(0xffffffffu, psum, o);
    if ((tid & 31) == 0) red[tid >> 5] = psum;
    __syncthreads();
    if (tid == 0) {
        float s = 0.0f;
        #pragma unroll
        for (int i = 0; i < 8; i++) s += red[i];
        g_planesum[plane] = s;
    }

    // z-DFT: thread handles w = tid&63, kz in {g, g+4, (g==0? 8)} where g = tid>>6.
    // g is warp-uniform -> twiddle loads are smem broadcasts.
    {
        const int w = tid & 63;
        const int g = tid >> 6;
        const int kz0 = g, kz1 = g + 4;
        float re0 = 0.f, im0 = 0.f, re1 = 0.f, im1 = 0.f, re2 = 0.f, im2 = 0.f;
        const float* row = &xs[w * 65];
        #pragma unroll 8
        for (int d = 0; d < 64; d++) {
            float v = row[d];
            float2 t0 = tw[(kz0 * d) & 63];
            re0 = fmaf(v, t0.x, re0); im0 = fmaf(-v, t0.y, im0);
            float2 t1 = tw[(kz1 * d) & 63];
            re1 = fmaf(v, t1.x, re1); im1 = fmaf(-v, t1.y, im1);
            if (g == 0) {
                float2 t2 = tw[(8 * d) & 63];
                re2 = fmaf(v, t2.x, re2); im2 = fmaf(-v, t2.y, im2);
            }
        }
        Zs[w * 9 + kz0] = make_float2(re0, im0);
        Zs[w * 9 + kz1] = make_float2(re1, im1);
        if (g == 0) Zs[w * 9 + 8] = make_float2(re2, im2);
    }
    __syncthreads();

    // y-DFT: 144 outputs (ky, kz)
    if (tid < NCOL) {
        const int ky = tid / 9;
        const int kz = tid % 9;
        float re = 0.f, im = 0.f;
        #pragma unroll 8
        for (int w = 0; w < 64; w++) {
            float2 z = Zs[w * 9 + kz];
            float2 t = tw[(ky * w) & 63];        // e^{-i theta}: (c, -s)
            re = fmaf(z.x, t.x, re); re = fmaf(z.y, t.y, re);
            im = fmaf(z.y, t.x, im); im = fmaf(-z.x, t.y, im);
        }
        g_Y[(size_t)plane * NCOL + tid] = make_float2(re, im);
    }
}

// ---------------------------------------------------------------------------
// Kernel 2: gate MLP (single block)
// ---------------------------------------------------------------------------
__global__ void __launch_bounds__(256) k_gates(const float* __restrict__ w1,
                                               const float* __restrict__ b1,
                                               const float* __restrict__ w2,
                                               const float* __restrict__ b2) {
    __shared__ float pooled_s[256];   // [b*64+c]
    __shared__ float hid_s[64];       // [b*16+j]
    const int tid = threadIdx.x;

    // pooled[b,c] = mean(x) = planesum / 64^3
    {
        float s = 0.0f;
        const float* ps = &g_planesum[tid * 64];
        #pragma unroll 8
        for (int h = 0; h < 64; h++) s += ps[h];
        pooled_s[tid] = s * INV_N3;
    }
    __syncthreads();

    if (tid < 64) {
        const int b = tid >> 4, j = tid & 15;
        float acc = b1[j];
        #pragma unroll 8
        for (int c = 0; c < 64; c++) acc = fmaf(pooled_s[b * 64 + c], w1[c * 16 + j], acc);
        hid_s[tid] = fmaxf(acc, 0.0f);
    }
    __syncthreads();

    for (int j2 = tid; j2 < 4 * GATE_DIM; j2 += 256) {
        const int b = j2 / GATE_DIM, m = j2 % GATE_DIM;
        float acc = b2[m];
        #pragma unroll
        for (int j = 0; j < 16; j++) acc = fmaf(hid_s[b * 16 + j], w2[j * GATE_DIM + m], acc);
        float sig = 1.0f / (1.0f + expf(-acc));
        g_gate[j2] = (sig - 1.0f) * INV_N3;     // fold irfftn normalization here
    }
}

// ---------------------------------------------------------------------------
// Kernel 3: per (b,c): x-DFT (16 modes) -> gate -> x-inverse, in place on g_Y
// ---------------------------------------------------------------------------
__global__ void __launch_bounds__(256) k_xstage() {
    __shared__ float2 As[NCOL * 17];   // [m][kx], pad 17 avoids 32-way conflicts
    __shared__ float2 tw[64];

    const int bc  = blockIdx.x;        // 0..255
    const int b   = bc >> 6;
    const int tid = threadIdx.x;
    fill_tw(tw, tid);
    __syncthreads();

    const float2* Yb = &g_Y[(size_t)bc * 64 * NCOL];

    // Phase 1: A[m][kx] = gate * sum_h Y[h][m] e^{-2pi i kx h/64}
    #pragma unroll
    for (int r = 0; r < 9; r++) {                 // 2304 / 256
        const int j  = tid + r * 256;
        const int m  = j >> 4;
        const int kx = j & 15;
        float re = 0.f, im = 0.f;
        #pragma unroll 8
        for (int h = 0; h < 64; h++) {
            float2 Yv = Yb[h * NCOL + m];
            float2 t  = tw[(kx * h) & 63];        // e^{-i theta}
            re = fmaf(Yv.x, t.x, re); re = fmaf(Yv.y, t.y, re);
            im = fmaf(Yv.y, t.x, im); im = fmaf(-Yv.x, t.y, im);
        }
        float gate = g_gate[b * GATE_DIM + kx * NCOL + m];
        As[m * 17 + kx] = make_float2(re * gate, im * gate);
    }
    __syncthreads();

    // Phase 2: Ynew[h][m] = sum_kx A[m][kx] e^{+2pi i kx h/64}
    float2* Yw = &g_Y[(size_t)bc * 64 * NCOL];
    #pragma unroll
    for (int r = 0; r < 36; r++) {                // 9216 / 256
        const int j = tid + r * 256;
        const int h = j / NCOL;
        const int m = j % NCOL;
        float re = 0.f, im = 0.f;
        #pragma unroll
        for (int kx = 0; kx < 16; kx++) {
            float2 A = As[m * 17 + kx];
            float2 t = tw[(kx * h) & 63];         // e^{+i theta}
            re = fmaf(A.x, t.x, re); re = fmaf(-A.y, t.y, re);
            im = fmaf(A.x, t.y, im); im = fmaf(A.y, t.x, im);
        }
        Yw[j] = make_float2(re, im);
    }
}

// ---------------------------------------------------------------------------
// Kernel 4: per-plane (b,c,h): y-inverse, Hermitian z-synthesis, out = x + delta
// ---------------------------------------------------------------------------
__global__ void __launch_bounds__(256) k_inv(const float* __restrict__ x,
                                             float* __restrict__ out) {
    __shared__ float2 Yrow[NCOL];
    __shared__ float2 B2s[64 * 9];     // [w][kz]
    __shared__ float2 tw[64];

    const int plane = blockIdx.x;
    const int tid   = threadIdx.x;
    fill_tw(tw, tid);
    if (tid < NCOL) Yrow[tid] = g_Y[(size_t)plane * NCOL + tid];
    __syncthreads();

    // y-inverse: B2[w][kz] = sum_ky Yrow[ky][kz] e^{+2pi i ky w/64}
    for (int j = tid; j < 576; j += 256) {
        const int w  = j / 9;
        const int kz = j % 9;
        float re = 0.f, im = 0.f;
        #pragma unroll
        for (int ky = 0; ky < 16; ky++) {
            float2 Yv = Yrow[ky * 9 + kz];
            float2 t  = tw[(ky * w) & 63];        // e^{+i theta}
            re = fmaf(Yv.x, t.x, re); re = fmaf(-Yv.y, t.y, re);
            im = fmaf(Yv.x, t.y, im); im = fmaf(Yv.y, t.x, im);
        }
        B2s[j] = make_float2(re, im);
    }
    __syncthreads();

    // z-synthesis: d constant per thread -> hoist twiddles to registers.
    // delta(d) = B2[w][0].re + 2*sum_{kz=1..8} Re(B2[w][kz] e^{+2pi i kz d/64})
    const int d  = tid & 63;
    const int wb = tid >> 6;
    float cs[8], ss[8];
    #pragma unroll
    for (int kz = 1; kz <= 8; kz++) {
        float2 t = tw[(kz * d) & 63];
        cs[kz - 1] = t.x; ss[kz - 1] = t.y;
    }
    const size_t base = (size_t)plane * 4096;
    #pragma unroll
    for (int k = 0; k < 16; k++) {
        const int w = wb + 4 * k;
        const float2* Brow = &B2s[w * 9];
        float acc = Brow[0].x;
        #pragma unroll
        for (int kz = 1; kz <= 8; kz++) {
            float2 Bv = Brow[kz];
            acc = fmaf(2.0f * Bv.x, cs[kz - 1], acc);
            acc = fmaf(-2.0f * Bv.y, ss[kz - 1], acc);
        }
        const size_t idx = base + (size_t)w * 64 + d;
        out[idx] = x[idx] + acc;
    }
}

// ---------------------------------------------------------------------------
extern "C" void kernel_launch(void* const* d_in, const int* in_sizes, int n_in,
                              void* d_out, int out_size) {
    const float* x  = (const float*)d_in[0];
    const float* w1 = (const float*)d_in[1];
    const float* b1 = (const float*)d_in[2];
    const float* w2 = (const float*)d_in[3];
    const float* b2 = (const float*)d_in[4];
    float* out = (float*)d_out;

    k_fwd<<<NPLANES, 256>>>(x);
    k_gates<<<1, 256>>>(w1, b1, w2, b2);
    k_xstage<<<NBC, 256>>>();
    k_inv<<<NPLANES, 256>>>(x, out);
}

// round 4
// speedup vs baseline: 2.0059x; 2.0059x over previous
#include <cuda_runtime.h>
#include <math.h>

// x: [B=4, C=64, H=64, W=64, D=64] fp32
// out = x + irfftn(delta), delta = (gate-1)*rfftn(x) on corner [16,16,9]
#define NPLANES 16384   // B*C*H
#define GATE_DIM 2304   // 16*16*9
#define NCOL    144     // 16 ky * 9 kz

__device__ float2 g_Y[NPLANES * NCOL];     // 18.9 MB intermediate spectrum
__device__ float  g_planesum[NPLANES];
__device__ float  g_gate[4 * GATE_DIM];    // (sigmoid-1)/64^3

#define INV_N3 (1.0f / 262144.0f)

// tw[t] = (cos(2*pi*t/64), sin(2*pi*t/64))
__device__ __forceinline__ void fill_tw(float2* tw, int tid) {
    if (tid < 64) {
        float s, c;
        sincospif((float)tid * (1.0f / 32.0f), &s, &c);
        tw[tid] = make_float2(c, s);
    }
}

// ---------------------------------------------------------------------------
// Kernel 1: per-plane (b,c,h): plane sum, folded z-DFT (9 modes), folded y-DFT
// ---------------------------------------------------------------------------
__global__ void __launch_bounds__(256) k_fwd(const float* __restrict__ x) {
    __shared__ float  xs[64 * 65];        // [w][d], stride 65
    __shared__ float2 Zs[64 * 9];         // [w][kz]
    __shared__ float2 tw[64];
    __shared__ float  red[8];

    const int plane = blockIdx.x;
    const int tid   = threadIdx.x;
    fill_tw(tw, tid);

    // Vectorized plane load + pooling sum
    const float4* xp4 = (const float4*)(x + (size_t)plane * 4096);
    float psum = 0.0f;
    #pragma unroll
    for (int k = 0; k < 4; k++) {
        const int i4 = k * 256 + tid;         // float4 index
        float4 v = xp4[i4];
        const int base = i4 * 4;
        float* dst = &xs[(base >> 6) * 65 + (base & 63)];
        dst[0] = v.x; dst[1] = v.y; dst[2] = v.z; dst[3] = v.w;
        psum += (v.x + v.y) + (v.z + v.w);
    }
    #pragma unroll
    for (int o = 16; o > 0; o >>= 1) psum += __shfl_down_sync(0xffffffffu, psum, o);
    if ((tid & 31) == 0) red[tid >> 5] = psum;
    __syncthreads();
    if (tid == 0) {
        float s = 0.0f;
        #pragma unroll
        for (int i = 0; i < 8; i++) s += red[i];
        g_planesum[plane] = s;
    }

    // Folded z-DFT: thread (g = tid>>6, w = tid&63); kz in {g, g+4, 8 if g==0}
    {
        const int w = tid & 63;
        const int g = tid >> 6;
        const int kz0 = g, kz1 = g + 4;
        const float sg0 = (kz0 & 1) ? -1.0f : 1.0f;   // cos(32*kz)
        const float sg1 = (kz1 & 1) ? -1.0f : 1.0f;
        const float* row = &xs[w * 65];
        const float x0 = row[0], x32 = row[32];
        float re0 = x0 + sg0 * x32, im0 = 0.f;
        float re1 = x0 + sg1 * x32, im1 = 0.f;
        float re2 = x0 + x32,       im2 = 0.f;        // kz=8: (-1)^8=+1
        #pragma unroll 31
        for (int dp = 1; dp <= 31; dp++) {
            float a = row[dp], b = row[64 - dp];
            float e = a + b, o = a - b;
            float2 t0 = tw[(kz0 * dp) & 63];
            re0 = fmaf(e, t0.x, re0); im0 = fmaf(-o, t0.y, im0);
            float2 t1 = tw[(kz1 * dp) & 63];
            re1 = fmaf(e, t1.x, re1); im1 = fmaf(-o, t1.y, im1);
            if (g == 0) {
                float2 t2 = tw[(8 * dp) & 63];
                re2 = fmaf(e, t2.x, re2); im2 = fmaf(-o, t2.y, im2);
            }
        }
        Zs[w * 9 + kz0] = make_float2(re0, im0);
        Zs[w * 9 + kz1] = make_float2(re1, im1);
        if (g == 0) Zs[w * 9 + 8] = make_float2(re2, im2);
    }
    __syncthreads();

    // Folded y-DFT: 144 outputs (ky,kz)
    if (tid < NCOL) {
        const int ky = tid / 9;
        const int kz = tid % 9;
        const float sg = (ky & 1) ? -1.0f : 1.0f;
        float2 z0 = Zs[kz], z32 = Zs[32 * 9 + kz];
        float re = z0.x + sg * z32.x;
        float im = z0.y + sg * z32.y;
        #pragma unroll 31
        for (int wp = 1; wp <= 31; wp++) {
            float2 za = Zs[wp * 9 + kz];
            float2 zb = Zs[(64 - wp) * 9 + kz];
            float sx = za.x + zb.x, dxx = za.x - zb.x;
            float sy = za.y + zb.y, dy  = za.y - zb.y;
            float2 t = tw[(ky * wp) & 63];
            re = fmaf(sx, t.x, re); re = fmaf(dy, t.y, re);
            im = fmaf(sy, t.x, im); im = fmaf(-dxx, t.y, im);
        }
        g_Y[(size_t)plane * NCOL + tid] = make_float2(re, im);
    }
}

// ---------------------------------------------------------------------------
// Kernel 2: gate MLP (single block)
// ---------------------------------------------------------------------------
__global__ void __launch_bounds__(256) k_gates(const float* __restrict__ w1,
                                               const float* __restrict__ b1,
                                               const float* __restrict__ w2,
                                               const float* __restrict__ b2) {
    __shared__ float pooled_s[256];
    __shared__ float hid_s[64];
    const int tid = threadIdx.x;
    {
        float s = 0.0f;
        const float* ps = &g_planesum[tid * 64];
        #pragma unroll 8
        for (int h = 0; h < 64; h++) s += ps[h];
        pooled_s[tid] = s * INV_N3;
    }
    __syncthreads();
    if (tid < 64) {
        const int b = tid >> 4, j = tid & 15;
        float acc = b1[j];
        #pragma unroll 8
        for (int c = 0; c < 64; c++) acc = fmaf(pooled_s[b * 64 + c], w1[c * 16 + j], acc);
        hid_s[tid] = fmaxf(acc, 0.0f);
    }
    __syncthreads();
    for (int j2 = tid; j2 < 4 * GATE_DIM; j2 += 256) {
        const int b = j2 / GATE_DIM, m = j2 % GATE_DIM;
        float acc = b2[m];
        #pragma unroll
        for (int j = 0; j < 16; j++) acc = fmaf(hid_s[b * 16 + j], w2[j * GATE_DIM + m], acc);
        float sig = 1.0f / (1.0f + expf(-acc));
        g_gate[j2] = (sig - 1.0f) * INV_N3;
    }
}

// ---------------------------------------------------------------------------
// Kernel 3: per (bc, 36-mode chunk): folded x-DFT -> gate -> folded x-inverse
// grid = 256*4 = 1024
// ---------------------------------------------------------------------------
#define MCH 36
__global__ void __launch_bounds__(256) k_xstage() {
    __shared__ float2 Ys[64 * MCH];       // [h][mLoc]
    __shared__ float2 As[MCH * 17];       // [mLoc][kx], pad 17
    __shared__ float2 tw[64];

    const int bx    = blockIdx.x;
    const int bc    = bx >> 2;
    const int b     = bc >> 6;
    const int m0    = (bx & 3) * MCH;
    const int tid   = threadIdx.x;
    fill_tw(tw, tid);

    float2* Yg = &g_Y[(size_t)bc * 64 * NCOL];

    // Stage Y chunk into smem (coalesced 288B runs)
    for (int j = tid; j < 64 * MCH; j += 256) {
        const int h = j / MCH, mL = j % MCH;
        Ys[j] = Yg[h * NCOL + m0 + mL];
    }
    __syncthreads();

    // Phase 1: A[mL][kx] = gate * sum_h Ys[h][mL] e^{-2pi i kx h/64}  (folded)
    for (int j = tid; j < MCH * 16; j += 256) {
        const int kx = j / MCH;
        const int mL = j % MCH;
        const float sg = (kx & 1) ? -1.0f : 1.0f;
        float2 z0 = Ys[mL], z32 = Ys[32 * MCH + mL];
        float re = z0.x + sg * z32.x;
        float im = z0.y + sg * z32.y;
        #pragma unroll 31
        for (int hp = 1; hp <= 31; hp++) {
            float2 za = Ys[hp * MCH + mL];
            float2 zb = Ys[(64 - hp) * MCH + mL];
            float sx = za.x + zb.x, dxx = za.x - zb.x;
            float sy = za.y + zb.y, dy  = za.y - zb.y;
            float2 t = tw[(kx * hp) & 63];
            re = fmaf(sx, t.x, re); re = fmaf(dy, t.y, re);
            im = fmaf(sy, t.x, im); im = fmaf(-dxx, t.y, im);
        }
        float gate = g_gate[b * GATE_DIM + kx * NCOL + m0 + mL];
        As[mL * 17 + kx] = make_float2(re * gate, im * gate);
    }
    __syncthreads();

    // Phase 2: Ynew[h][mL] = sum_kx A e^{+2pi i kx h/64}; pairs (h, 64-h).
    // hp=0 handles h=0 and h=32.
    for (int j = tid; j < 32 * MCH; j += 256) {
        const int hp = j / MCH;
        const int mL = j % MCH;
        float P = 0.f, Q = 0.f, R = 0.f, S = 0.f;
        #pragma unroll
        for (int kx = 0; kx < 16; kx++) {
            float2 A = As[mL * 17 + kx];
            float2 t = tw[(kx * hp) & 63];
            P = fmaf(A.x, t.x, P); Q = fmaf(A.y, t.y, Q);
            R = fmaf(A.y, t.x, R); S = fmaf(A.x, t.y, S);
        }
        if (hp == 0) {
            // h=0: (P, R). h=32: alternating-sign sums.
            float P32 = 0.f, R32 = 0.f;
            #pragma unroll
            for (int kx = 0; kx < 16; kx++) {
                float2 A = As[mL * 17 + kx];
                float sg = (kx & 1) ? -1.0f : 1.0f;
                P32 = fmaf(A.x, sg, P32); R32 = fmaf(A.y, sg, R32);
            }
            Yg[m0 + mL]              = make_float2(P, R);
            Yg[32 * NCOL + m0 + mL]  = make_float2(P32, R32);
        } else {
            Yg[hp * NCOL + m0 + mL]        = make_float2(P - Q, S + R);
            Yg[(64 - hp) * NCOL + m0 + mL] = make_float2(P + Q, R - S);
        }
    }
}

// ---------------------------------------------------------------------------
// Kernel 4: per-plane: folded y-inverse, folded Hermitian z-synthesis, add x
// ---------------------------------------------------------------------------
__global__ void __launch_bounds__(256) k_inv(const float* __restrict__ x,
                                             float* __restrict__ out) {
    __shared__ float2 Yrow[NCOL];
    __shared__ float2 B2s[64 * 9];     // [w][kz]
    __shared__ float2 tw[64];

    const int plane = blockIdx.x;
    const int tid   = threadIdx.x;
    fill_tw(tw, tid);
    if (tid < NCOL) Yrow[tid] = g_Y[(size_t)plane * NCOL + tid];
    __syncthreads();

    // Folded y-inverse: tasks 0..278 generic pairs, 279..287 w=0, 288..296 w=32
    for (int j = tid; j < 297; j += 256) {
        if (j < 279) {
            const int wp = j / 9 + 1;
            const int kz = j % 9;
            float rc = 0.f, rs = 0.f, ic = 0.f, is_ = 0.f;
            #pragma unroll
            for (int ky = 0; ky < 16; ky++) {
                float2 Yv = Yrow[ky * 9 + kz];
                float2 t  = tw[(ky * wp) & 63];
                rc = fmaf(Yv.x, t.x, rc); rs  = fmaf(Yv.y, t.y, rs);
                ic = fmaf(Yv.y, t.x, ic); is_ = fmaf(Yv.x, t.y, is_);
            }
            B2s[wp * 9 + kz]        = make_float2(rc - rs, is_ + ic);
            B2s[(64 - wp) * 9 + kz] = make_float2(rc + rs, ic - is_);
        } else if (j < 288) {
            const int kz = j - 279;       // w = 0: twiddle = 1
            float re = 0.f, im = 0.f;
            #pragma unroll
            for (int ky = 0; ky < 16; ky++) {
                float2 Yv = Yrow[ky * 9 + kz];
                re += Yv.x; im += Yv.y;
            }
            B2s[kz] = make_float2(re, im);
        } else {
            const int kz = j - 288;       // w = 32: twiddle = (-1)^ky
            float re = 0.f, im = 0.f;
            #pragma unroll
            for (int ky = 0; ky < 16; ky++) {
                float2 Yv = Yrow[ky * 9 + kz];
                float sg = (ky & 1) ? -1.0f : 1.0f;
                re = fmaf(Yv.x, sg, re); im = fmaf(Yv.y, sg, im);
            }
            B2s[32 * 9 + kz] = make_float2(re, im);
        }
    }
    __syncthreads();

    // Folded z-synthesis: lane dp handles d=dp and d=64-dp (dp=0 -> d=0 and 32)
    const int dp = tid & 31;
    const int wg = tid >> 5;              // warp id: w uniform per warp
    float cs[8], ss[8];
    #pragma unroll
    for (int kz = 1; kz <= 8; kz++) {
        float2 t = tw[(kz * dp) & 63];
        cs[kz - 1] = t.x; ss[kz - 1] = t.y;
    }
    const size_t base = (size_t)plane * 4096;
    const int d2 = (dp == 0) ? 32 : (64 - dp);
    #pragma unroll
    for (int k = 0; k < 8; k++) {
        const int w = wg * 8 + k;
        float2 Br[9];
        #pragma unroll
        for (int kz = 0; kz < 9; kz++) Br[kz] = B2s[w * 9 + kz];  // broadcast
        float Ac = 0.f, Asum = 0.f;
        #pragma unroll
        for (int kz = 1; kz <= 8; kz++) {
            Ac   = fmaf(Br[kz].x, cs[kz - 1], Ac);
            Asum = fmaf(Br[kz].y, ss[kz - 1], Asum);
        }
        const float b0 = Br[0].x;
        float v1 = fmaf(2.0f, Ac - Asum, b0);
        float v2 = fmaf(2.0f, Ac + Asum, b0);
        if (dp == 0) {
            float A32 = 0.f;
            #pragma unroll
            for (int kz = 1; kz <= 8; kz++) {
                float sg = (kz & 1) ? -1.0f : 1.0f;
                A32 = fmaf(Br[kz].x, sg, A32);
            }
            v2 = fmaf(2.0f, A32, b0);
        }
        const size_t i1 = base + (size_t)w * 64 + dp;
        const size_t i2 = base + (size_t)w * 64 + d2;
        out[i1] = x[i1] + v1;
        out[i2] = x[i2] + v2;
    }
}

// ---------------------------------------------------------------------------
extern "C" void kernel_launch(void* const* d_in, const int* in_sizes, int n_in,
                              void* d_out, int out_size) {
    const float* x  = (const float*)d_in[0];
    const float* w1 = (const float*)d_in[1];
    const float* b1 = (const float*)d_in[2];
    const float* w2 = (const float*)d_in[3];
    const float* b2 = (const float*)d_in[4];
    float* out = (float*)d_out;

    k_fwd<<<NPLANES, 256>>>(x);
    k_gates<<<1, 256>>>(w1, b1, w2, b2);
    k_xstage<<<1024, 256>>>();
    k_inv<<<NPLANES, 256>>>(x, out);
}